// round 2
// baseline (speedup 1.0000x reference)
#include <cuda_runtime.h>

// Problem constants
#define BB 32
#define TT 24
#define NN 325
#define DD 64
#define NHEAD 8
#define DHEAD 8

#define NB 8                  // nodes per CTA
#define MROWS (NB * TT)       // 192 rows per CTA tile
#define NTILES ((NN + NB - 1) / NB)   // 41
#define NTHREADS 256

#define ST 68                 // smem row stride (floats), banks (4r)%32 -> conflict-free
#define WST 64                // weight smem stride

// shared memory layout (floats)
#define BUF_FLOATS (MROWS * ST)       // 13056
#define XS_OFF 0
#define QS_OFF (BUF_FLOATS)
#define KS_OFF (2 * BUF_FLOATS)
#define VS_OFF (3 * BUF_FLOATS)
#define WS_OFF (4 * BUF_FLOATS)
#define SMEM_FLOATS (4 * BUF_FLOATS + 64 * 64)   // 56320
#define SMEM_BYTES (SMEM_FLOATS * 4)             // 225280 B -> 1 CTA/SM

typedef unsigned long long ull;

// ---------------------------------------------------------------------------
// Packed f32x2 helpers (sm_103a dual-rate FFMA)
// ---------------------------------------------------------------------------
__device__ __forceinline__ ull pack2(float x) {
    ull r;
    asm("mov.b64 %0, {%1, %1};" : "=l"(r) : "f"(x));
    return r;
}
__device__ __forceinline__ ull ffma2(ull a, ull b, ull c) {
    ull d;
    asm("fma.rn.f32x2 %0, %1, %2, %3;" : "=l"(d) : "l"(a), "l"(b), "l"(c));
    return d;
}
__device__ __forceinline__ float2 unpack2(ull v) {
    float2 r;
    asm("mov.b64 {%0, %1}, %2;" : "=f"(r.x), "=f"(r.y) : "l"(v));
    return r;
}

// ---------------------------------------------------------------------------
// Stage one 64x64 weight matrix into shared memory (coalesced float4).
// ---------------------------------------------------------------------------
__device__ __forceinline__ void load_weight(float* __restrict__ Wsm,
                                            const float* __restrict__ Wg,
                                            int tid) {
#pragma unroll
    for (int i = 0; i < 4; ++i) {
        int idx = (tid + i * NTHREADS) * 4;   // 1024 float4 total
        *(float4*)(Wsm + idx) = *(const float4*)(Wg + idx);
    }
}

// ---------------------------------------------------------------------------
// 192x64 = [192x64] @ [64x64] GEMM core. Thread tile 6 rows x 8 cols,
// 32 row-groups x 8 col-groups = 256 threads. Accumulators packed f32x2.
// ---------------------------------------------------------------------------
__device__ __forceinline__ void gemm_core(const float* __restrict__ A,
                                          const float* __restrict__ Wsm,
                                          ull acc[6][4], int r0, int c0) {
#pragma unroll
    for (int i = 0; i < 6; ++i)
#pragma unroll
        for (int j = 0; j < 4; ++j) acc[i][j] = 0ull;

#pragma unroll 2
    for (int kk = 0; kk < 64; kk += 4) {
        float4 xf[6];
#pragma unroll
        for (int i = 0; i < 6; ++i)
            xf[i] = *(const float4*)(A + (r0 + i) * ST + kk);

        ull w2[4][4];
#pragma unroll
        for (int k = 0; k < 4; ++k) {
            ulonglong2 wa = *(const ulonglong2*)(Wsm + (kk + k) * WST + c0);
            ulonglong2 wb = *(const ulonglong2*)(Wsm + (kk + k) * WST + c0 + 4);
            w2[k][0] = wa.x; w2[k][1] = wa.y;
            w2[k][2] = wb.x; w2[k][3] = wb.y;
        }
#pragma unroll
        for (int k = 0; k < 4; ++k) {
#pragma unroll
            for (int i = 0; i < 6; ++i) {
                const float* xv = &xf[i].x;
                ull xx = pack2(xv[k]);
                acc[i][0] = ffma2(xx, w2[k][0], acc[i][0]);
                acc[i][1] = ffma2(xx, w2[k][1], acc[i][1]);
                acc[i][2] = ffma2(xx, w2[k][2], acc[i][2]);
                acc[i][3] = ffma2(xx, w2[k][3], acc[i][3]);
            }
        }
    }
}

// smem -> smem epilogue with bias (+ optional ReLU)
template <bool RELU>
__device__ __forceinline__ void gemm_tile(const float* __restrict__ A,
                                          const float* __restrict__ Wsm,
                                          const float* __restrict__ bias,
                                          float* __restrict__ outs,
                                          int tid) {
    const int rg = tid >> 3;
    const int cg = tid & 7;
    const int r0 = rg * 6;
    const int c0 = cg * 8;
    ull acc[6][4];
    gemm_core(A, Wsm, acc, r0, c0);

    float4 b0 = *(const float4*)(bias + c0);
    float4 b1 = *(const float4*)(bias + c0 + 4);
#pragma unroll
    for (int i = 0; i < 6; ++i) {
        float2 p0 = unpack2(acc[i][0]);
        float2 p1 = unpack2(acc[i][1]);
        float2 p2 = unpack2(acc[i][2]);
        float2 p3 = unpack2(acc[i][3]);
        float4 r0v = make_float4(p0.x + b0.x, p0.y + b0.y, p1.x + b0.z, p1.y + b0.w);
        float4 r1v = make_float4(p2.x + b1.x, p2.y + b1.y, p3.x + b1.z, p3.y + b1.w);
        if (RELU) {
            r0v.x = fmaxf(r0v.x, 0.f); r0v.y = fmaxf(r0v.y, 0.f);
            r0v.z = fmaxf(r0v.z, 0.f); r0v.w = fmaxf(r0v.w, 0.f);
            r1v.x = fmaxf(r1v.x, 0.f); r1v.y = fmaxf(r1v.y, 0.f);
            r1v.z = fmaxf(r1v.z, 0.f); r1v.w = fmaxf(r1v.w, 0.f);
        }
        *(float4*)(outs + (r0 + i) * ST + c0) = r0v;
        *(float4*)(outs + (r0 + i) * ST + c0 + 4) = r1v;
    }
}

// smem -> global epilogue (final layer), bias, no ReLU, node guard
__device__ __forceinline__ void gemm_out(const float* __restrict__ A,
                                         const float* __restrict__ Wsm,
                                         const float* __restrict__ bias,
                                         float* __restrict__ Y,
                                         int b, int n0, int tid) {
    const int rg = tid >> 3;
    const int cg = tid & 7;
    const int r0 = rg * 6;
    const int c0 = cg * 8;
    ull acc[6][4];
    gemm_core(A, Wsm, acc, r0, c0);

    float4 b0 = *(const float4*)(bias + c0);
    float4 b1 = *(const float4*)(bias + c0 + 4);
#pragma unroll
    for (int i = 0; i < 6; ++i) {
        int row = r0 + i;
        int node = row / TT;
        int t = row - node * TT;
        int n = n0 + node;
        if (n < NN) {
            float2 p0 = unpack2(acc[i][0]);
            float2 p1 = unpack2(acc[i][1]);
            float2 p2 = unpack2(acc[i][2]);
            float2 p3 = unpack2(acc[i][3]);
            float4 r0v = make_float4(p0.x + b0.x, p0.y + b0.y, p1.x + b0.z, p1.y + b0.w);
            float4 r1v = make_float4(p2.x + b1.x, p2.y + b1.y, p3.x + b1.z, p3.y + b1.w);
            float* dst = Y + ((size_t)(b * TT + t) * NN + n) * DD + c0;
            *(float4*)(dst) = r0v;
            *(float4*)(dst + 4) = r1v;
        }
    }
}

// ---------------------------------------------------------------------------
// Per-(node, t, head) attention: masked softmax over temporal axis (s >= t).
// Masked fill underflows to exact 0 after exp(x - max), matching -2^15+1.
// ---------------------------------------------------------------------------
__device__ __forceinline__ void attention(const float* __restrict__ Qs,
                                          const float* __restrict__ Ks,
                                          const float* __restrict__ Vs,
                                          float* __restrict__ Os,
                                          int tid) {
    const float scale = 0.3535533905932738f;  // 1/sqrt(8)
#pragma unroll 1
    for (int iter = 0; iter < NB * TT * NHEAD / NTHREADS; ++iter) {
        int task = iter * NTHREADS + tid;     // 0..1535
        int h = task & 7;
        int t = (task >> 3) % TT;
        int node = task / (TT * NHEAD);
        int base = node * TT;
        int hc = h * DHEAD;

        float4 q0 = *(const float4*)(Qs + (base + t) * ST + hc);
        float4 q1 = *(const float4*)(Qs + (base + t) * ST + hc + 4);
        q0.x *= scale; q0.y *= scale; q0.z *= scale; q0.w *= scale;
        q1.x *= scale; q1.y *= scale; q1.z *= scale; q1.w *= scale;

        float p[TT];
        float m = -1e30f;
#pragma unroll
        for (int s = 0; s < TT; ++s) {
            float4 k0 = *(const float4*)(Ks + (base + s) * ST + hc);
            float4 k1 = *(const float4*)(Ks + (base + s) * ST + hc + 4);
            float dot = q0.x * k0.x;
            dot = fmaf(q0.y, k0.y, dot);
            dot = fmaf(q0.z, k0.z, dot);
            dot = fmaf(q0.w, k0.w, dot);
            dot = fmaf(q1.x, k1.x, dot);
            dot = fmaf(q1.y, k1.y, dot);
            dot = fmaf(q1.z, k1.z, dot);
            dot = fmaf(q1.w, k1.w, dot);
            dot = (s >= t) ? dot : -1e30f;
            p[s] = dot;
            m = fmaxf(m, dot);
        }
        float sum = 0.0f;
#pragma unroll
        for (int s = 0; s < TT; ++s) {
            float e = __expf(p[s] - m);
            p[s] = e;
            sum += e;
        }
        float inv = 1.0f / sum;

        float o[8] = {0, 0, 0, 0, 0, 0, 0, 0};
#pragma unroll
        for (int s = 0; s < TT; ++s) {
            float4 v0 = *(const float4*)(Vs + (base + s) * ST + hc);
            float4 v1 = *(const float4*)(Vs + (base + s) * ST + hc + 4);
            o[0] = fmaf(p[s], v0.x, o[0]);
            o[1] = fmaf(p[s], v0.y, o[1]);
            o[2] = fmaf(p[s], v0.z, o[2]);
            o[3] = fmaf(p[s], v0.w, o[3]);
            o[4] = fmaf(p[s], v1.x, o[4]);
            o[5] = fmaf(p[s], v1.y, o[5]);
            o[6] = fmaf(p[s], v1.z, o[6]);
            o[7] = fmaf(p[s], v1.w, o[7]);
        }
        float4 r0 = make_float4(o[0] * inv, o[1] * inv, o[2] * inv, o[3] * inv);
        float4 r1 = make_float4(o[4] * inv, o[5] * inv, o[6] * inv, o[7] * inv);
        *(float4*)(Os + (base + t) * ST + hc) = r0;
        *(float4*)(Os + (base + t) * ST + hc + 4) = r1;
    }
}

// ---------------------------------------------------------------------------
// Fused kernel: one CTA per (batch, 8-node tile).
// ---------------------------------------------------------------------------
__global__ void __launch_bounds__(NTHREADS, 1)
temporal_attention_fused(const float* __restrict__ X,
                         const float* __restrict__ Wq, const float* __restrict__ bq,
                         const float* __restrict__ Wk, const float* __restrict__ bk,
                         const float* __restrict__ Wv, const float* __restrict__ bv,
                         const float* __restrict__ Wf1, const float* __restrict__ bf1,
                         const float* __restrict__ Wf2, const float* __restrict__ bf2,
                         float* __restrict__ Y) {
    extern __shared__ float smem[];
    float* Xs = smem + XS_OFF;   // reused for attention output
    float* Qs = smem + QS_OFF;   // reused for FC1 hidden
    float* Ks = smem + KS_OFF;
    float* Vs = smem + VS_OFF;
    float* Ws = smem + WS_OFF;

    const int tid = threadIdx.x;
    const int n0 = blockIdx.x * NB;
    const int b = blockIdx.y;

    // Load X tile: rows = node*24 + t, zero-fill out-of-range nodes.
#pragma unroll 2
    for (int i = tid; i < MROWS * 16; i += NTHREADS) {
        int row = i >> 4;
        int f4 = i & 15;
        int node = row / TT;
        int t = row - node * TT;
        int n = n0 + node;
        float4 v = make_float4(0.f, 0.f, 0.f, 0.f);
        if (n < NN)
            v = *(const float4*)(X + ((size_t)(b * TT + t) * NN + n) * DD + f4 * 4);
        *(float4*)(Xs + row * ST + f4 * 4) = v;
    }
    load_weight(Ws, Wq, tid);
    __syncthreads();

    gemm_tile<true>(Xs, Ws, bq, Qs, tid);      // q = relu(X@Wq + bq)
    __syncthreads();
    load_weight(Ws, Wk, tid);
    __syncthreads();
    gemm_tile<true>(Xs, Ws, bk, Ks, tid);      // k
    __syncthreads();
    load_weight(Ws, Wv, tid);
    __syncthreads();
    gemm_tile<true>(Xs, Ws, bv, Vs, tid);      // v
    __syncthreads();

    // Attention (writes into Xs) while also staging Wf1 (Ws free after v).
    load_weight(Ws, Wf1, tid);
    attention(Qs, Ks, Vs, Xs, tid);
    __syncthreads();

    gemm_tile<true>(Xs, Ws, bf1, Qs, tid);     // h = relu(out@Wf1 + bf1) -> Qs
    __syncthreads();
    load_weight(Ws, Wf2, tid);
    __syncthreads();
    gemm_out(Qs, Ws, bf2, Y, b, n0, tid);      // y = h@Wf2 + bf2 -> global
}

// ---------------------------------------------------------------------------
// kernel_launch: inputs per metadata order:
// 0=X 1=STE(unused) 2=Wq 3=bq 4=Wk 5=bk 6=Wv 7=bv 8=Wf1 9=bf1 10=Wf2 11=bf2
// ---------------------------------------------------------------------------
extern "C" void kernel_launch(void* const* d_in, const int* in_sizes, int n_in,
                              void* d_out, int out_size) {
    const float* X   = (const float*)d_in[0];
    const float* Wq  = (const float*)d_in[2];
    const float* bq  = (const float*)d_in[3];
    const float* Wk  = (const float*)d_in[4];
    const float* bk  = (const float*)d_in[5];
    const float* Wv  = (const float*)d_in[6];
    const float* bv  = (const float*)d_in[7];
    const float* Wf1 = (const float*)d_in[8];
    const float* bf1 = (const float*)d_in[9];
    const float* Wf2 = (const float*)d_in[10];
    const float* bf2 = (const float*)d_in[11];
    float* Y = (float*)d_out;

    cudaFuncSetAttribute(temporal_attention_fused,
                         cudaFuncAttributeMaxDynamicSharedMemorySize, SMEM_BYTES);

    dim3 grid(NTILES, BB);
    temporal_attention_fused<<<grid, NTHREADS, SMEM_BYTES>>>(
        X, Wq, bq, Wk, bk, Wv, bv, Wf1, bf1, Wf2, bf2, Y);
}